// round 16
// baseline (speedup 1.0000x reference)
#include <cuda_runtime.h>
#include <math.h>

// Problem constants (fixed by the reference)
#define NN      100000
#define EMAX    1600000
#define FIN     128
#define HCC     64          // heads*hid = 2*32
#define OUTC    40
#define NEG     0.2f
#define BN_EPS  1e-5f

// ---------------- scratch (device globals; no runtime allocation) -----------
__device__ float  g_h  [(size_t)NN * HCC];   // h of current layer
__device__ float  g_x1 [(size_t)NN * HCC];   // x1, later xj = max(x1,x2)
__device__ float2 g_asrc[NN];
__device__ float2 g_adst[NN];
__device__ int    g_rowptr[NN + 1];
__device__ int    g_col[EMAX];
__device__ int    g_deg[NN];
__device__ int    g_cur[NN];
__device__ float  g_bns[HCC];
__device__ float  g_bnb[HCC];

// ---------------- init: zero counters + BN fold (block 0) --------------------
__global__ void k_init(const float* __restrict__ gamma, const float* __restrict__ beta,
                       const float* __restrict__ mean,  const float* __restrict__ var)
{
    int i = blockIdx.x * blockDim.x + threadIdx.x;
    if (i < NN) { g_deg[i] = 0; g_cur[i] = 0; }
    if (blockIdx.x == 0 && threadIdx.x < HCC) {
        int c = threadIdx.x;
        float s = gamma[c] * rsqrtf(var[c] + BN_EPS);
        g_bns[c] = s;
        g_bnb[c] = beta[c] - mean[c] * s;
    }
}

__global__ void k_hist(const int* __restrict__ dst, int E)
{
    int i = blockIdx.x * blockDim.x + threadIdx.x;
    if (i < E) atomicAdd(&g_deg[dst[i]], 1);
}

// single-block exclusive scan of g_deg -> g_rowptr (proven correct in R12)
__global__ void k_scan()
{
    __shared__ int sums[1024];
    const int t  = threadIdx.x;
    const int CH = (NN + 1023) / 1024;           // 98
    int b = t * CH;
    int e = b + CH; if (e > NN) e = NN;
    if (b > NN) b = NN;
    int s = 0;
    for (int i = b; i < e; i++) s += __ldg(&g_deg[i]);
    sums[t] = s;
    __syncthreads();
    for (int off = 1; off < 1024; off <<= 1) {
        int v = 0;
        if (t >= off) v = sums[t - off];
        __syncthreads();
        sums[t] += v;
        __syncthreads();
    }
    int run = sums[t] - s;                       // exclusive base
    for (int i = b; i < e; i++) { g_rowptr[i] = run; run += g_deg[i]; }
    if (t == 1023) g_rowptr[NN] = run;
}

__global__ void k_scatter(const int* __restrict__ src, const int* __restrict__ dst, int E)
{
    int i = blockIdx.x * blockDim.x + threadIdx.x;
    if (i < E) {
        int d = dst[i];
        int p = atomicAdd(&g_cur[d], 1);
        g_col[__ldg(&g_rowptr[d]) + p] = src[i];
    }
}

// ---------------- GAT aggregation: one warp per destination node -------------
// Lanes cooperatively fetch up to 32 edges (col + asrc) in ONE memory round,
// compute per-edge softmax numerators, then gather h rows with one LDG.64 per
// edge (lane owns channels 2*lane, 2*lane+1), unrolled x4 for MLP.
// No segment-max (logits O(5), exp cannot overflow; softmax shift-invariant).
// mode 0: out = elu(bn(res + b))          (layer 1, writes x1)
// mode 1: out = max(out, res + b)         (layer 2 + JK max, out == x1 buffer)
__global__ void __launch_bounds__(256) k_gat(const float* __restrict__ h,
                                             const float* __restrict__ b,
                                             float* __restrict__ out, int mode)
{
    const unsigned FULL = 0xffffffffu;
    int n    = (blockIdx.x * blockDim.x + threadIdx.x) >> 5;
    int lane = threadIdx.x & 31;
    if (n >= NN) return;

    int start = g_rowptr[n];
    int end   = g_rowptr[n + 1];
    float2 ad = g_adst[n];

    // self-loop contribution
    float2 asn = g_asrc[n];
    float t0 = asn.x + ad.x, t1 = asn.y + ad.y;
    float es0 = __expf(fmaxf(t0, NEG * t0));
    float es1 = __expf(fmaxf(t1, NEG * t1));
    float2 hn = *(const float2*)&h[(size_t)n * HCC + 2 * lane];
    float esel = (lane < 16) ? es0 : es1;
    float fx = esel * hn.x;
    float fy = esel * hn.y;
    float den0 = 0.f, den1 = 0.f;

    for (int base = start; base < end; base += 32) {
        int idx = base + lane;
        bool v  = idx < end;
        int  s  = v ? __ldg(&g_col[idx]) : 0;
        float ex0 = 0.f, ex1 = 0.f;
        if (v) {
            float2 as = g_asrc[s];
            float u0 = as.x + ad.x, u1 = as.y + ad.y;
            ex0 = __expf(fmaxf(u0, NEG * u0));
            ex1 = __expf(fmaxf(u1, NEG * u1));
        }
        den0 += ex0;
        den1 += ex1;
        int cnt = end - base; if (cnt > 32) cnt = 32;
        int j = 0;
        for (; j + 4 <= cnt; j += 4) {
#pragma unroll
            for (int u = 0; u < 4; u++) {
                int   sj = __shfl_sync(FULL, s,   j + u);
                float e0 = __shfl_sync(FULL, ex0, j + u);
                float e1 = __shfl_sync(FULL, ex1, j + u);
                float2 h2 = *(const float2*)&h[(size_t)sj * HCC + 2 * lane];
                float e = (lane < 16) ? e0 : e1;
                fx += e * h2.x;
                fy += e * h2.y;
            }
        }
        for (; j < cnt; j++) {
            int   sj = __shfl_sync(FULL, s,   j);
            float e0 = __shfl_sync(FULL, ex0, j);
            float e1 = __shfl_sync(FULL, ex1, j);
            float2 h2 = *(const float2*)&h[(size_t)sj * HCC + 2 * lane];
            float e = (lane < 16) ? e0 : e1;
            fx += e * h2.x;
            fy += e * h2.y;
        }
    }
#pragma unroll
    for (int o = 16; o; o >>= 1) {
        den0 += __shfl_xor_sync(FULL, den0, o);
        den1 += __shfl_xor_sync(FULL, den1, o);
    }
    den0 += es0;
    den1 += es1;
    float inv0 = 1.f / (den0 + 1e-16f);
    float inv1 = 1.f / (den1 + 1e-16f);
    float inv  = (lane < 16) ? inv0 : inv1;
    float rx = fx * inv;
    float ry = fy * inv;

    int c0 = 2 * lane;
    size_t oo = (size_t)n * HCC + c0;
    float2 bb = *(const float2*)&b[c0];
    if (mode == 0) {
        float2 sc = *(const float2*)&g_bns[c0];
        float2 sh = *(const float2*)&g_bnb[c0];
        rx = (rx + bb.x) * sc.x + sh.x;
        ry = (ry + bb.y) * sc.y + sh.y;
        rx = rx > 0.f ? rx : expm1f(rx);
        ry = ry > 0.f ? ry : expm1f(ry);
        *(float2*)&out[oo] = make_float2(rx, ry);
    } else {
        rx += bb.x;
        ry += bb.y;
        float2 prev = *(const float2*)&out[oo];
        *(float2*)&out[oo] = make_float2(fmaxf(prev.x, rx), fmaxf(prev.y, ry));
    }
}

// ---------------- tiled fp32 GEMM: [N,K] x [K,WC] (+bias) (+fused alpha) -----
// 64-node x CP-col tile, 4x4 micro-tile, FULL K resident in dynamic smem.
// Compile-time NT so fill loops fully unroll (high MLP); A-tile via float4.
template<int K, int CP, int WC, int NT, bool BIAS, bool ALPHA>
__global__ void __launch_bounds__(NT) k_gemm(const float* __restrict__ A,
                                             const float* __restrict__ W,
                                             const float* __restrict__ bias,
                                             float* __restrict__ Out,
                                             const float* __restrict__ a_s,
                                             const float* __restrict__ a_d)
{
    extern __shared__ float sm[];
    float* Xs = sm;                 // [K][68]
    float* Ws = sm + K * 68;        // [K][CP]
    __shared__ float sAs[64][2];
    __shared__ float sAd[64][2];

    const int TX = CP / 4;
    int tid  = threadIdx.x;
    int tx   = tid % TX, ty = tid / TX;
    int base = blockIdx.x * 64;

    // fill A tile with float4 loads (coalesced, fully unrolled -> MLP)
    {
        const int TOT = 64 * K / 4;                  // float4 count
        const int CEIL = (TOT + NT - 1) / NT;
#pragma unroll
        for (int r = 0; r < CEIL; r++) {
            int q = tid + r * NT;
            if (q < TOT) {
                int nl = (4 * q) / K;
                int k0 = (4 * q) % K;
                int node = base + nl;
                float4 v = make_float4(0.f, 0.f, 0.f, 0.f);
                if (node < NN) v = *(const float4*)&A[(size_t)node * K + k0];
                Xs[(k0 + 0) * 68 + nl] = v.x;
                Xs[(k0 + 1) * 68 + nl] = v.y;
                Xs[(k0 + 2) * 68 + nl] = v.z;
                Xs[(k0 + 3) * 68 + nl] = v.w;
            }
        }
    }
    // fill W tile (scalar, fully unrolled)
    {
        const int TOT = K * CP;
        const int CEIL = (TOT + NT - 1) / NT;
#pragma unroll
        for (int r = 0; r < CEIL; r++) {
            int idx = tid + r * NT;
            if (idx < TOT) {
                int k = idx / CP, c = idx % CP;
                Ws[idx] = (c < WC) ? __ldg(&W[(size_t)k * WC + c]) : 0.f;
            }
        }
    }
    if (ALPHA && tid < 64) {
        sAs[tid][0] = 0.f; sAs[tid][1] = 0.f;
        sAd[tid][0] = 0.f; sAd[tid][1] = 0.f;
    }
    __syncthreads();

    float acc[4][4];
#pragma unroll
    for (int i = 0; i < 4; i++)
#pragma unroll
        for (int j = 0; j < 4; j++) acc[i][j] = 0.f;

#pragma unroll 8
    for (int k = 0; k < K; k++) {
        float4 a  = *(const float4*)&Xs[k * 68 + 4 * ty];
        float4 b4 = *(const float4*)&Ws[k * CP + 4 * tx];
        acc[0][0] += a.x * b4.x; acc[0][1] += a.x * b4.y; acc[0][2] += a.x * b4.z; acc[0][3] += a.x * b4.w;
        acc[1][0] += a.y * b4.x; acc[1][1] += a.y * b4.y; acc[1][2] += a.y * b4.z; acc[1][3] += a.y * b4.w;
        acc[2][0] += a.z * b4.x; acc[2][1] += a.z * b4.y; acc[2][2] += a.z * b4.z; acc[2][3] += a.z * b4.w;
        acc[3][0] += a.w * b4.x; acc[3][1] += a.w * b4.y; acc[3][2] += a.w * b4.z; acc[3][3] += a.w * b4.w;
    }

    // write outputs (float4 stores where the 4-col group is fully in range)
#pragma unroll
    for (int i = 0; i < 4; i++) {
        int node = base + 4 * ty + i;
        if (node >= NN) continue;
        int c = 4 * tx;
        float4 v = make_float4(acc[i][0], acc[i][1], acc[i][2], acc[i][3]);
        if (BIAS) {
            v.x += bias[c]; v.y += bias[c + 1]; v.z += bias[c + 2]; v.w += bias[c + 3];
        }
        if (c + 3 < WC) {
            *(float4*)&Out[(size_t)node * WC + c] = v;
        } else {
            if (c     < WC) Out[(size_t)node * WC + c]     = v.x;
            if (c + 1 < WC) Out[(size_t)node * WC + c + 1] = v.y;
            if (c + 2 < WC) Out[(size_t)node * WC + c + 2] = v.z;
            if (c + 3 < WC) Out[(size_t)node * WC + c + 3] = v.w;
        }
    }

    // fused attention logits: asrc[n][hd] = sum_c out[n][c]*a_s[c]
    if (ALPHA) {
        int hd = (4 * tx) >> 5;            // thread's 4 cols lie in one head
        float w_s[4], w_d[4];
#pragma unroll
        for (int j = 0; j < 4; j++) { w_s[j] = a_s[4 * tx + j]; w_d[j] = a_d[4 * tx + j]; }
#pragma unroll
        for (int i = 0; i < 4; i++) {
            float pa = 0.f, pd = 0.f;
#pragma unroll
            for (int j = 0; j < 4; j++) { pa += acc[i][j] * w_s[j]; pd += acc[i][j] * w_d[j]; }
            atomicAdd(&sAs[4 * ty + i][hd], pa);
            atomicAdd(&sAd[4 * ty + i][hd], pd);
        }
        __syncthreads();
        if (tid < 64) {
            int node = base + tid;
            if (node < NN) {
                g_asrc[node] = make_float2(sAs[tid][0], sAs[tid][1]);
                g_adst[node] = make_float2(sAd[tid][0], sAd[tid][1]);
            }
        }
    }
}

// ---------------- launcher ---------------------------------------------------
extern "C" void kernel_launch(void* const* d_in, const int* in_sizes, int n_in,
                              void* d_out, int out_size)
{
    const float* node_feat = (const float*)d_in[0];
    const int*   edge      = (const int*)  d_in[1];
    const float* W1        = (const float*)d_in[2];
    const float* a_src1    = (const float*)d_in[3];
    const float* a_dst1    = (const float*)d_in[4];
    const float* b1        = (const float*)d_in[5];
    const float* bn_gamma  = (const float*)d_in[6];
    const float* bn_beta   = (const float*)d_in[7];
    const float* bn_mean   = (const float*)d_in[8];
    const float* bn_var    = (const float*)d_in[9];
    const float* W2        = (const float*)d_in[10];
    const float* a_src2    = (const float*)d_in[11];
    const float* a_dst2    = (const float*)d_in[12];
    const float* b2        = (const float*)d_in[13];
    const float* Wf        = (const float*)d_in[14];
    const float* bf        = (const float*)d_in[15];
    float* outp            = (float*)d_out;

    const int E = in_sizes[1] / 2;
    const int* src = edge;
    const int* dst = edge + E;

    const int GEMM_BLKS = (NN + 63) / 64;          // 1563
    const int WARP_BLKS = (NN + 7) / 8;            // 12500 (8 warps/block)
    const int E_BLKS    = (E + 255) / 256;
    const int N_BLKS    = (NN + 255) / 256;

    // dynamic smem sizes
    const int SM1 = (FIN * 68 + FIN * 64) * 4;     // 67584 B
    const int SM2 = (HCC * 68 + HCC * 64) * 4;     // 33792 B
    const int SMF = (HCC * 68 + HCC * 48) * 4;     // 29696 B
    cudaFuncSetAttribute((const void*)k_gemm<FIN, 64, 64, 256, false, true>,
                         cudaFuncAttributeMaxDynamicSharedMemorySize, SM1);

    // CSR build (launch #4 = k_scatter gets profiled by ncu -s 5 -c 1)
    k_init<<<N_BLKS, 256>>>(bn_gamma, bn_beta, bn_mean, bn_var);   // 1
    k_hist<<<E_BLKS, 256>>>(dst, E);                               // 2
    k_scan<<<1, 1024>>>();                                         // 3
    k_scatter<<<E_BLKS, 256>>>(src, dst, E);                       // 4

    // layer 1 (GEMM + fused alpha, then aggregate+BN+ELU)
    k_gemm<FIN, 64, 64, 256, false, true><<<GEMM_BLKS, 256, SM1>>>(
        node_feat, W1, nullptr, g_h, a_src1, a_dst1);              // 5
    k_gat<<<WARP_BLKS, 256>>>(g_h, b1, g_x1, 0);                   // 6

    // layer 2 (GEMM + fused alpha, then aggregate + JK max into g_x1)
    k_gemm<HCC, 64, 64, 256, false, true><<<GEMM_BLKS, 256, SM2>>>(
        g_x1, W2, nullptr, g_h, a_src2, a_dst2);                   // 7
    k_gat<<<WARP_BLKS, 256>>>(g_h, b2, g_x1, 1);                   // 8

    // final projection 64 -> 40 (+bf)
    k_gemm<HCC, 48, OUTC, 192, true, false><<<GEMM_BLKS, 192, SMF>>>(
        g_x1, Wf, bf, outp, nullptr, nullptr);                     // 9
}